// round 11
// baseline (speedup 1.0000x reference)
#include <cuda_runtime.h>
#include <math.h>

// Problem constants
#define B_    128
#define N_    32
#define T_    50
#define H_    128
#define NT_   1600           // N_*T_
#define HOPS_ 8

// Output layout: tuple (BW, BA, neigh_r) flattened in order
#define BW_OFF   ((size_t)0)
#define BA_OFF   ((size_t)(B_) * NT_)                       // 204800
#define NR_OFF   (BA_OFF + (size_t)(B_) * HOPS_ * NT_)      // 204800 + 1638400

// scratch: per-(b,hop,block) partial sums of exps (50 K1 blocks per b)
__device__ float g_part[B_ * HOPS_ * 50];

// ---- packed f32x2 helpers (Blackwell FFMA2 path, PTX-only) -----------------
__device__ __forceinline__ unsigned long long pack2(float lo, float hi) {
    unsigned long long r;
    asm("mov.b64 %0, {%1, %2};" : "=l"(r) : "f"(lo), "f"(hi));
    return r;
}
__device__ __forceinline__ void unpack2(unsigned long long v, float& lo, float& hi) {
    asm("mov.b64 {%0, %1}, %2;" : "=f"(lo), "=f"(hi) : "l"(v));
}
__device__ __forceinline__ unsigned long long mul2(unsigned long long a,
                                                   unsigned long long b) {
    unsigned long long d;
    asm("mul.rn.f32x2 %0, %1, %2;" : "=l"(d) : "l"(a), "l"(b));
    return d;
}
__device__ __forceinline__ unsigned long long ffma2(unsigned long long a,
                                                    unsigned long long b,
                                                    unsigned long long c) {
    unsigned long long d;
    asm("fma.rn.f32x2 %0, %1, %2, %3;" : "=l"(d) : "l"(a), "l"(b), "l"(c));
    return d;
}

// ---------------------------------------------------------------------------
// K1: fused neigh_r copy + logits + exp + per-block hop partial sums.
// Block covers 16 n x 2 t = 32 rows of one b. 8 warps x 4 rows/warp; a warp's
// 4 rows share t -> node row u loaded ONCE per warp.
// Epilogue: warp a holds hop a's 32 exps -> butterfly -> g_part (deterministic).
// ---------------------------------------------------------------------------
#define SA_  132
#define ST_  64

__global__ __launch_bounds__(256, 3) void k1_fused(
    const float* __restrict__ node,   // [B, T, H]
    const float* __restrict__ neigh,  // [B, N, T, H]
    const int*   __restrict__ nn,     // [B]
    const float* __restrict__ W,      // [HOPS, H]
    const float* __restrict__ bias,   // [HOPS]
    float* __restrict__ out)
{
    __shared__ float stage[HOPS_ * SA_];   // [hop][toff][nloc][k]

    const int tid  = threadIdx.x;
    const int wid  = tid >> 5;
    const int lane = tid & 31;

    // grid = B * 2 * 25 : bid -> (b, ng, tg)
    const int bid = blockIdx.x;
    const int b   = bid / 50;
    const int rem = bid - b * 50;        // block index within b: 0..49
    const int ng  = rem / 25;            // 0..1  -> n0 = ng*16
    const int tg  = rem - ng * 25;       // 0..24 -> t0 = tg*2
    const int n0  = ng * 16;
    const int t0  = tg * 2;

    const int nh   = wid >> 1;           // 0..3 : n sub-group
    const int toff = wid & 1;            // 0..1 : t within block
    const int t    = t0 + toff;
    const int nA   = n0 + nh * 4;        // first n of this warp

    // W packed as hop-pairs: wp[a2][c] = {W[2a2][4l+c], W[2a2+1][4l+c]}
    unsigned long long wp[4][4];
#pragma unroll
    for (int a2 = 0; a2 < 4; a2++) {
        const float4 wa = __ldg((const float4*)(W + (2 * a2)     * H_) + lane);
        const float4 wb = __ldg((const float4*)(W + (2 * a2 + 1) * H_) + lane);
        wp[a2][0] = pack2(wa.x, wb.x);
        wp[a2][1] = pack2(wa.y, wb.y);
        wp[a2][2] = pack2(wa.z, wb.z);
        wp[a2][3] = pack2(wa.w, wb.w);
    }

    // base row = (b, nA, t); successive rows step n by 1 -> +T_*H_ floats
    const size_t row0 = ((size_t)(b * N_ + nA) * T_ + t) * H_;
    const float4* nbase = (const float4*)(neigh + row0) + lane;
    float4*       obase = (float4*)(out + NR_OFF + row0) + lane;

    // one node row per warp, reused for all 4 rows
    const float4 u = __ldg((const float4*)(node + ((size_t)b * T_ + t) * H_) + lane);

    // batched streaming loads (MLP) + copy
    float4 v[4];
#pragma unroll
    for (int i = 0; i < 4; i++)
        v[i] = __ldcs(nbase + (size_t)i * (T_ * H_ / 4));
#pragma unroll
    for (int i = 0; i < 4; i++)
        __stcs(obase + (size_t)i * (T_ * H_ / 4), v[i]);

#pragma unroll
    for (int i = 0; i < 4; i++) {
        const int nloc = nh * 4 + i;     // 0..15

        const float px = v[i].x * u.x, py = v[i].y * u.y,
                    pz = v[i].z * u.z, pw = v[i].w * u.w;
        const unsigned long long d0 = pack2(px, px);
        const unsigned long long d1 = pack2(py, py);
        const unsigned long long d2 = pack2(pz, pz);
        const unsigned long long d3 = pack2(pw, pw);

        unsigned long long acc[4];
#pragma unroll
        for (int a2 = 0; a2 < 4; a2++) {
            acc[a2] = mul2(d0, wp[a2][0]);
            acc[a2] = ffma2(d1, wp[a2][1], acc[a2]);
            acc[a2] = ffma2(d2, wp[a2][2], acc[a2]);
            acc[a2] = ffma2(d3, wp[a2][3], acc[a2]);
        }

        float part[HOPS_];
        unpack2(acc[0], part[0], part[1]);
        unpack2(acc[1], part[2], part[3]);
        unpack2(acc[2], part[4], part[5]);
        unpack2(acc[3], part[6], part[7]);

        // ---- 14-shuffle fold reduction: stop at 4 residue-partials/hop ----
#pragma unroll
        for (int a = 0; a < HOPS_; a++)
            part[a] += __shfl_xor_sync(0xffffffffu, part[a], 16);

        float q0 = (lane < 16) ? part[0] : part[4];
        float q1 = (lane < 16) ? part[1] : part[5];
        float q2 = (lane < 16) ? part[2] : part[6];
        float q3 = (lane < 16) ? part[3] : part[7];
        q0 += __shfl_xor_sync(0xffffffffu, q0, 8);
        q1 += __shfl_xor_sync(0xffffffffu, q1, 8);
        q2 += __shfl_xor_sync(0xffffffffu, q2, 8);
        q3 += __shfl_xor_sync(0xffffffffu, q3, 8);

        float r0 = ((lane & 8) == 0) ? q0 : q2;
        float r1 = ((lane & 8) == 0) ? q1 : q3;
        r0 += __shfl_xor_sync(0xffffffffu, r0, 4);
        r1 += __shfl_xor_sync(0xffffffffu, r1, 4);

        // lane l holds residue-partial k=(l&3) of hop a=(l>>2)
        const float s = ((lane & 4) == 0) ? r0 : r1;
        stage[(lane >> 2) * SA_ + toff * ST_ + nloc * 4 + (lane & 3)] = s;
    }
    __syncthreads();

    // epilogue: warp a finishes hop a's 32 (n,t): LDS.128 + exp + BA store,
    // then butterfly-sums its 32 exps -> per-block partial (deterministic).
    {
        const int a    = wid;                      // hop
        const int j    = lane;                     // row slot
        const int tofe = j >> 4;                   // 0..1
        const int nle  = j & 15;                   // 0..15
        const float4 p = *(const float4*)&stage[a * SA_ + tofe * ST_ + nle * 4];
        const float dot = (p.x + p.y) + (p.z + p.w);
        const float rscale = rsqrtf((float)__ldg(nn));
        const float logit = (dot + __ldg(bias + a)) * rscale;
        // exp without max-subtraction: logits are O(1) by construction,
        // normalization cancels any shift exactly.
        const float ev = __expf(logit);
        out[BA_OFF + ((size_t)(b * HOPS_ + a)) * NT_
            + (size_t)(n0 + nle) * T_ + t0 + tofe] = ev;

        float ssum = ev;
#pragma unroll
        for (int off = 16; off; off >>= 1)
            ssum += __shfl_xor_sync(0xffffffffu, ssum, off);
        if (lane == 0)
            g_part[((size_t)(b * HOPS_ + a)) * 50 + rem] = ssum;
    }
}

// ---------------------------------------------------------------------------
// K2: normalize + BW, grid = B*4 (4 slabs of 100 float4-slots per b).
// 128 threads: 4 warps first reduce the 50 K1-partials per hop (fixed order,
// deterministic) -> inv_s; then 100 threads do the 8-hop load/scale/store + BW.
// 512 blocks -> 4x latency coverage on the DRAM-resident BA read.
// ---------------------------------------------------------------------------
__global__ __launch_bounds__(128) void k2_norm_bw(float* __restrict__ out)
{
    __shared__ float inv_s[HOPS_];

    const int tid  = threadIdx.x;
    const int wid  = tid >> 5;
    const int lane = tid & 31;
    const int b    = blockIdx.x >> 2;
    const int slab = blockIdx.x & 3;

    // inv_s: warp w handles hops w and w+4
#pragma unroll
    for (int h = wid; h < HOPS_; h += 4) {
        const float* P = g_part + ((size_t)(b * HOPS_ + h)) * 50;
        float s = (lane < 25) ? (P[lane] + P[lane + 25]) : 0.f;
#pragma unroll
        for (int off = 16; off; off >>= 1)
            s += __shfl_xor_sync(0xffffffffu, s, off);
        if (lane == 0) inv_s[h] = 1.0f / s;
    }
    __syncthreads();

    if (tid < 100) {
        const int slot = slab * 100 + tid;        // float4 slot in [0,400)
        float* BAb = out + BA_OFF + (size_t)b * HOPS_ * NT_;

        // batched loads (MLP=8)
        float4 va[HOPS_];
#pragma unroll
        for (int a = 0; a < HOPS_; a++)
            va[a] = ((const float4*)(BAb + (size_t)a * NT_))[slot];

        float4 acc = make_float4(0.f, 0.f, 0.f, 0.f);
#pragma unroll
        for (int a = 0; a < HOPS_; a++) {
            const float iv = inv_s[a];
            float4 v = va[a];
            v.x *= iv; v.y *= iv; v.z *= iv; v.w *= iv;
            ((float4*)(BAb + (size_t)a * NT_))[slot] = v;
            acc.x += v.x; acc.y += v.y; acc.z += v.z; acc.w += v.w;
        }
        ((float4*)(out + (size_t)b * NT_))[slot] = acc;   // BW
    }
}

// ---------------------------------------------------------------------------
extern "C" void kernel_launch(void* const* d_in, const int* in_sizes, int n_in,
                              void* d_out, int out_size)
{
    const float* node  = (const float*)d_in[0];  // [B,T,H]
    const float* neigh = (const float*)d_in[1];  // [B,N,T,H]
    const int*   nn    = (const int*)  d_in[2];  // [B]
    const float* W     = (const float*)d_in[3];  // [HOPS,H]
    const float* bias  = (const float*)d_in[4];  // [HOPS]
    float* out = (float*)d_out;

    (void)in_sizes; (void)n_in; (void)out_size;

    // K1: grid = B * 2 * 25 = 6400 blocks (16 n x 2 t per block)
    k1_fused<<<B_ * 50, 256>>>(node, neigh, nn, W, bias, out);
    // K2: grid = B * 4 slabs, 128 threads
    k2_norm_bw<<<B_ * 4, 128>>>(out);
}